// round 9
// baseline (speedup 1.0000x reference)
#include <cuda_runtime.h>
#include <math.h>

#define U_DIM   100000
#define B_DIM   128
#define K_DIM   500
#define NRUNS   10
#define NPAIRS  124750.0      // 500*499/2
#define GRID    592           // 4 blocks/SM on >=148 SMs -> all co-resident
#define TPB     128
#define NWARPS  (GRID * 4)
#define NGATHER (NRUNS * K_DIM)   // 5000 warp-units
#define NUNITS  (NRUNS * 72)      // 720: 36 tile-pairs * 2 row-halves * 10 runs

// ---------------- device scratch ----------------
__device__ double   g_sums[NRUNS][5];               // sr, sd, srr, sdd, srd
__device__ float    g_xhat[NRUNS * K_DIM * B_DIM];  // unit-norm centered vectors
__device__ float    g_px[NRUNS * 512];
__device__ float    g_py[NRUNS * 512];
__device__ unsigned g_bar  = 0;                     // phase-1 grid barrier
__device__ unsigned g_fin  = 0;                     // finish counter
__device__ unsigned g_next = 0;                     // phase-2 work-steal cursor

__global__ __launch_bounds__(TPB, 4)
void k_all(const float* __restrict__ feat,
           const float* __restrict__ pos,
           const int*   __restrict__ neigh,
           float*       __restrict__ out)
{
    __shared__ int   sChoice[NRUNS];
    __shared__ __align__(16) float As[32][32];   // [kk][row-node]  (32-row A half)
    __shared__ __align__(16) float Bs[32][64];   // [kk][col-node]
    __shared__ float pax[32], pay[32], pbx[64], pby[64];
    __shared__ double redbuf[4][5];
    __shared__ int sUnit;
    __shared__ int sLast;

    const int tid  = threadIdx.x;
    const int bid  = blockIdx.x;
    const int lane = tid & 31;
    const int wid  = tid >> 5;

    // ---------- phase 0: threefry2x32 -> choices ----------
    if (tid == 0) {
        unsigned ks[3];
        ks[0] = 0u; ks[1] = 42u; ks[2] = 0u ^ 42u ^ 0x1BD11BDAu;
        const int rot[2][4] = {{13, 15, 26, 6}, {17, 29, 16, 24}};
        for (int p = 0; p < 5; p++) {
            unsigned x0 = (unsigned)p + ks[0];
            unsigned x1 = (unsigned)(p + 5) + ks[1];
            for (int g = 0; g < 5; g++) {
                #pragma unroll
                for (int q = 0; q < 4; q++) {
                    int rr = rot[g & 1][q];
                    x0 += x1;
                    x1 = (x1 << rr) | (x1 >> (32 - rr));
                    x1 ^= x0;
                }
                x0 += ks[(g + 1) % 3];
                x1 += ks[(g + 2) % 3] + (unsigned)(g + 1);
            }
            // jax _randint (nbits=32): offset = ((bits>>16)%100)*96 + (bits&0xFFFF)%100, mod 100
            sChoice[p]     = (int)((((x0 >> 16) % 100u) * 96u + (x0 & 0xFFFFu) % 100u) % 100u);
            sChoice[p + 5] = (int)((((x1 >> 16) % 100u) * 96u + (x1 & 0xFFFFu) % 100u) % 100u);
        }
    }
    if (bid == 0 && tid < NRUNS * 5) ((double*)g_sums)[tid] = 0.0;
    __syncthreads();

    // ---------- phase 1: gather (warp-per-unit, MLP=4, no block syncs) ----------
    {
        const int gwid = bid * 4 + wid;
        for (int u = gwid; u < NGATHER; u += NWARPS) {
            int r = u / K_DIM;
            int k = u - r * K_DIM;
            int ind = neigh[sChoice[r] * K_DIM + k];

            const float* fcol = feat + ind;
            float v0 = fcol[(lane      ) * U_DIM];
            float v1 = fcol[(lane +  32) * U_DIM];
            float v2 = fcol[(lane +  64) * U_DIM];
            float v3 = fcol[(lane +  96) * U_DIM];

            float s = (v0 + v1) + (v2 + v3);
            #pragma unroll
            for (int o = 16; o > 0; o >>= 1) s += __shfl_xor_sync(0xFFFFFFFFu, s, o);
            float mean = s * (1.0f / 128.0f);

            float x0 = v0 - mean, x1 = v1 - mean, x2 = v2 - mean, x3 = v3 - mean;
            float q = (x0 * x0 + x1 * x1) + (x2 * x2 + x3 * x3);
            #pragma unroll
            for (int o = 16; o > 0; o >>= 1) q += __shfl_xor_sync(0xFFFFFFFFu, q, o);
            float scale = rsqrtf(q);

            float* dst = &g_xhat[(r * K_DIM + k) * B_DIM];
            dst[lane      ] = x0 * scale;
            dst[lane +  32] = x1 * scale;
            dst[lane +  64] = x2 * scale;
            dst[lane +  96] = x3 * scale;

            if (lane == 0) {
                g_px[r * 512 + k] = pos[ind * 2 + 0];
                g_py[r * 512 + k] = pos[ind * 2 + 1];
            }
        }
    }

    // ---------- grid barrier: atomic arrive, volatile-load poll ----------
    __syncthreads();
    if (tid == 0) {
        __threadfence();
        atomicAdd(&g_bar, 1u);
        volatile unsigned* vb = &g_bar;
        while (*vb < (unsigned)GRID) __nanosleep(128);
    }
    __syncthreads();

    // ---------- phase 2: pairs, dynamic work stealing (720 units, 32x64) ----------
    const int tx = tid & 15;    // 0..15 -> 4 cols each
    const int ty = tid >> 4;    // 0..7  -> 4 rows each

    for (;;) {
        if (tid == 0) sUnit = (int)atomicAdd(&g_next, 1u);
        __syncthreads();
        int unit = sUnit;
        if (unit >= NUNITS) break;

        int r = unit / 72;
        int w = unit - r * 72;
        int t = w >> 1;          // 0..35 lower-tri 64-tile pair
        int h = w & 1;           // row half
        int ti = 0;
        while ((ti + 1) * (ti + 2) / 2 <= t) ti++;
        int tj = t - ti * (ti + 1) / 2;
        int i0 = ti * 64 + h * 32;   // 32 A rows
        int j0 = tj * 64;            // 64 B cols

        if (tid < 32) {
            int i = i0 + tid;
            pax[tid] = (i < K_DIM) ? g_px[r * 512 + i] : 0.0f;
            pay[tid] = (i < K_DIM) ? g_py[r * 512 + i] : 0.0f;
        } else if (tid < 96) {
            int n = tid - 32;
            int j = j0 + n;
            pbx[n] = (j < K_DIM) ? g_px[r * 512 + j] : 0.0f;
            pby[n] = (j < K_DIM) ? g_py[r * 512 + j] : 0.0f;
        }

        // load mappings
        int anode = tid >> 2;            // 0..31
        int akg   = (tid & 3) * 8;       // 8 consecutive k
        int bnode = tid >> 1;            // 0..63
        int bkg   = (tid & 1) * 16;      // 16 consecutive k
        int gA = i0 + anode;
        int gB = j0 + bnode;
        const float* baseA = (gA < K_DIM) ? &g_xhat[(r * K_DIM + gA) * B_DIM] : 0;
        const float* baseB = (gB < K_DIM) ? &g_xhat[(r * K_DIM + gB) * B_DIM] : 0;

        float acc[4][4];
        #pragma unroll
        for (int uu = 0; uu < 4; uu++)
            #pragma unroll
            for (int vv = 0; vv < 4; vv++) acc[uu][vv] = 0.0f;

        for (int chunk = 0; chunk < 4; chunk++) {
            int ka = chunk * 32 + akg;
            int kb = chunk * 32 + bkg;
            float4 a0 = make_float4(0.f, 0.f, 0.f, 0.f), a1 = a0;
            float4 b0 = a0, b1 = a0, b2 = a0, b3 = a0;
            if (baseA) { a0 = *(const float4*)(baseA + ka); a1 = *(const float4*)(baseA + ka + 4); }
            if (baseB) {
                b0 = *(const float4*)(baseB + kb);      b1 = *(const float4*)(baseB + kb + 4);
                b2 = *(const float4*)(baseB + kb + 8);  b3 = *(const float4*)(baseB + kb + 12);
            }
            As[akg + 0][anode] = a0.x; As[akg + 1][anode] = a0.y; As[akg + 2][anode] = a0.z; As[akg + 3][anode] = a0.w;
            As[akg + 4][anode] = a1.x; As[akg + 5][anode] = a1.y; As[akg + 6][anode] = a1.z; As[akg + 7][anode] = a1.w;
            Bs[bkg +  0][bnode] = b0.x; Bs[bkg +  1][bnode] = b0.y; Bs[bkg +  2][bnode] = b0.z; Bs[bkg +  3][bnode] = b0.w;
            Bs[bkg +  4][bnode] = b1.x; Bs[bkg +  5][bnode] = b1.y; Bs[bkg +  6][bnode] = b1.z; Bs[bkg +  7][bnode] = b1.w;
            Bs[bkg +  8][bnode] = b2.x; Bs[bkg +  9][bnode] = b2.y; Bs[bkg + 10][bnode] = b2.z; Bs[bkg + 11][bnode] = b2.w;
            Bs[bkg + 12][bnode] = b3.x; Bs[bkg + 13][bnode] = b3.y; Bs[bkg + 14][bnode] = b3.z; Bs[bkg + 15][bnode] = b3.w;
            __syncthreads();

            #pragma unroll 8
            for (int kk = 0; kk < 32; kk++) {
                float4 a4 = *(const float4*)&As[kk][ty * 4];
                float4 b4 = *(const float4*)&Bs[kk][tx * 4];
                float av[4] = {a4.x, a4.y, a4.z, a4.w};
                float bv[4] = {b4.x, b4.y, b4.z, b4.w};
                #pragma unroll
                for (int uu = 0; uu < 4; uu++)
                    #pragma unroll
                    for (int vv = 0; vv < 4; vv++)
                        acc[uu][vv] = fmaf(av[uu], bv[vv], acc[uu][vv]);
            }
            __syncthreads();
        }

        // pair statistics (fp64 moments)
        double sr = 0.0, sd = 0.0, srr = 0.0, sdd = 0.0, srd = 0.0;
        #pragma unroll
        for (int uu = 0; uu < 4; uu++) {
            int iloc = ty * 4 + uu;
            int i = i0 + iloc;
            #pragma unroll
            for (int vv = 0; vv < 4; vv++) {
                int jloc = tx * 4 + vv;
                int j = j0 + jloc;
                if (i < K_DIM && j < K_DIM && i > j) {
                    float cr = acc[uu][vv];
                    float dx = pax[iloc] - pbx[jloc];
                    float dy = pay[iloc] - pby[jloc];
                    float ds = 1.0f / (sqrtf(dx * dx + dy * dy) + 1.0f);
                    sr  += (double)cr;
                    sd  += (double)ds;
                    srr += (double)cr * cr;
                    sdd += (double)ds * ds;
                    srd += (double)cr * ds;
                }
            }
        }
        #pragma unroll
        for (int o = 16; o > 0; o >>= 1) {
            sr  += __shfl_down_sync(0xFFFFFFFFu, sr,  o);
            sd  += __shfl_down_sync(0xFFFFFFFFu, sd,  o);
            srr += __shfl_down_sync(0xFFFFFFFFu, srr, o);
            sdd += __shfl_down_sync(0xFFFFFFFFu, sdd, o);
            srd += __shfl_down_sync(0xFFFFFFFFu, srd, o);
        }
        if (lane == 0) {
            redbuf[wid][0] = sr;  redbuf[wid][1] = sd;  redbuf[wid][2] = srr;
            redbuf[wid][3] = sdd; redbuf[wid][4] = srd;
        }
        __syncthreads();
        if (tid < 5) {
            double a5 = redbuf[0][tid] + redbuf[1][tid] + redbuf[2][tid] + redbuf[3][tid];
            atomicAdd(&g_sums[r][tid], a5);
        }
        __syncthreads();
    }

    // ---------- phase 3: last block finalizes ----------
    __syncthreads();
    if (tid == 0) {
        __threadfence();
        unsigned old = atomicAdd(&g_fin, 1u);
        sLast = (old == (unsigned)GRID - 1u) ? 1 : 0;
    }
    __syncthreads();
    if (sLast && tid == 0) {
        g_bar  = 0u;                      // reset for next replay (all blocks done)
        g_fin  = 0u;
        g_next = 0u;
        __threadfence();
        double acc = 0.0;
        for (int i = 0; i < NRUNS; i++) {
            volatile double* ps = &g_sums[i][0];
            double sr = ps[0], sd = ps[1], srr = ps[2], sdd = ps[3], srd = ps[4];
            double P = NPAIRS;
            double ca  = srr - sr * sr / P;
            double cb  = sdd - sd * sd / P;
            double cab = srd - sr * sd / P;
            acc += (1.0 - cab / sqrt(ca * cb)) * 0.5;
        }
        out[0] = (float)(acc / (double)NRUNS);
    }
}

// ---------------- launch ----------------
extern "C" void kernel_launch(void* const* d_in, const int* in_sizes, int n_in,
                              void* d_out, int out_size) {
    const float* feat  = (const float*)d_in[0];   // [128, 100000]
    const float* pos   = (const float*)d_in[1];   // [100000, 2]
    const int*   neigh = (const int*)  d_in[2];   // [100, 500]
    float* out = (float*)d_out;

    k_all<<<GRID, TPB>>>(feat, pos, neigh, out);
}

// round 11
// speedup vs baseline: 1.4821x; 1.4821x over previous
#include <cuda_runtime.h>
#include <math.h>

#define U_DIM   100000
#define B_DIM   128
#define K_DIM   500
#define NRUNS   10
#define NPAIRS  124750.0      // 500*499/2
#define GRID    592           // 4 blocks/SM on >=148 SMs -> all co-resident
#define TPB     128
#define NWARPS  (GRID * 4)
#define NGATHER (NRUNS * K_DIM)   // 5000 warp-units
#define NUNITS  (NRUNS * 72)      // 720: 36 tile-pairs * 2 row-halves * 10 runs

// ---------------- device scratch ----------------
__device__ double   g_sums[NRUNS][5];               // sr, sd, srr, sdd, srd
__device__ float    g_xhat[NRUNS * K_DIM * B_DIM];  // unit-norm centered vectors
__device__ float    g_px[NRUNS * 512];
__device__ float    g_py[NRUNS * 512];
__device__ unsigned g_bar  = 0;                     // phase-1 grid barrier
__device__ unsigned g_fin  = 0;                     // finish counter
__device__ unsigned g_next = 0;                     // phase-2 work-steal cursor

__global__ __launch_bounds__(TPB, 4)
void k_all(const float* __restrict__ feat,
           const float* __restrict__ pos,
           const int*   __restrict__ neigh,
           float*       __restrict__ out)
{
    __shared__ int   sChoice[NRUNS];
    __shared__ __align__(16) float As[32][32];   // [kk][row-node]  (32-row A half)
    __shared__ __align__(16) float Bs[32][64];   // [kk][col-node]
    __shared__ float pax[32], pay[32], pbx[64], pby[64];
    __shared__ float redbuf[4][5];               // fp32 warp partials
    __shared__ int sUnit;
    __shared__ int sLast;

    const int tid  = threadIdx.x;
    const int bid  = blockIdx.x;
    const int lane = tid & 31;
    const int wid  = tid >> 5;

    // ---------- phase 0: threefry2x32 -> choices ----------
    if (tid == 0) {
        unsigned ks[3];
        ks[0] = 0u; ks[1] = 42u; ks[2] = 0u ^ 42u ^ 0x1BD11BDAu;
        const int rot[2][4] = {{13, 15, 26, 6}, {17, 29, 16, 24}};
        for (int p = 0; p < 5; p++) {
            unsigned x0 = (unsigned)p + ks[0];
            unsigned x1 = (unsigned)(p + 5) + ks[1];
            for (int g = 0; g < 5; g++) {
                #pragma unroll
                for (int q = 0; q < 4; q++) {
                    int rr = rot[g & 1][q];
                    x0 += x1;
                    x1 = (x1 << rr) | (x1 >> (32 - rr));
                    x1 ^= x0;
                }
                x0 += ks[(g + 1) % 3];
                x1 += ks[(g + 2) % 3] + (unsigned)(g + 1);
            }
            // jax _randint (nbits=32): offset = ((bits>>16)%100)*96 + (bits&0xFFFF)%100, mod 100
            sChoice[p]     = (int)((((x0 >> 16) % 100u) * 96u + (x0 & 0xFFFFu) % 100u) % 100u);
            sChoice[p + 5] = (int)((((x1 >> 16) % 100u) * 96u + (x1 & 0xFFFFu) % 100u) % 100u);
        }
    }
    if (bid == 0 && tid < NRUNS * 5) ((double*)g_sums)[tid] = 0.0;
    __syncthreads();

    // ---------- phase 1: gather (warp-per-unit, MLP=4, no block syncs) ----------
    {
        const int gwid = bid * 4 + wid;
        for (int u = gwid; u < NGATHER; u += NWARPS) {
            int r = u / K_DIM;
            int k = u - r * K_DIM;
            int ind = neigh[sChoice[r] * K_DIM + k];

            const float* fcol = feat + ind;
            float v0 = fcol[(lane      ) * U_DIM];
            float v1 = fcol[(lane +  32) * U_DIM];
            float v2 = fcol[(lane +  64) * U_DIM];
            float v3 = fcol[(lane +  96) * U_DIM];

            float s = (v0 + v1) + (v2 + v3);
            #pragma unroll
            for (int o = 16; o > 0; o >>= 1) s += __shfl_xor_sync(0xFFFFFFFFu, s, o);
            float mean = s * (1.0f / 128.0f);

            float x0 = v0 - mean, x1 = v1 - mean, x2 = v2 - mean, x3 = v3 - mean;
            float q = (x0 * x0 + x1 * x1) + (x2 * x2 + x3 * x3);
            #pragma unroll
            for (int o = 16; o > 0; o >>= 1) q += __shfl_xor_sync(0xFFFFFFFFu, q, o);
            float scale = rsqrtf(q);

            float* dst = &g_xhat[(r * K_DIM + k) * B_DIM];
            dst[lane      ] = x0 * scale;
            dst[lane +  32] = x1 * scale;
            dst[lane +  64] = x2 * scale;
            dst[lane +  96] = x3 * scale;

            if (lane == 0) {
                g_px[r * 512 + k] = pos[ind * 2 + 0];
                g_py[r * 512 + k] = pos[ind * 2 + 1];
            }
        }
    }

    // ---------- grid barrier: atomic arrive, volatile-load poll ----------
    __syncthreads();
    if (tid == 0) {
        __threadfence();
        atomicAdd(&g_bar, 1u);
        volatile unsigned* vb = &g_bar;
        while (*vb < (unsigned)GRID) __nanosleep(128);
    }
    __syncthreads();

    // ---------- phase 2: pairs, dynamic work stealing (720 units, 32x64) ----------
    const int tx = tid & 15;    // 0..15 -> 4 cols each
    const int ty = tid >> 4;    // 0..7  -> 4 rows each

    for (;;) {
        if (tid == 0) sUnit = (int)atomicAdd(&g_next, 1u);
        __syncthreads();
        int unit = sUnit;
        if (unit >= NUNITS) break;

        int r = unit / 72;
        int w = unit - r * 72;
        int t = w >> 1;          // 0..35 lower-tri 64-tile pair
        int h = w & 1;           // row half
        int ti = 0;
        while ((ti + 1) * (ti + 2) / 2 <= t) ti++;
        int tj = t - ti * (ti + 1) / 2;
        int i0 = ti * 64 + h * 32;   // 32 A rows
        int j0 = tj * 64;            // 64 B cols

        if (tid < 32) {
            int i = i0 + tid;
            pax[tid] = (i < K_DIM) ? g_px[r * 512 + i] : 0.0f;
            pay[tid] = (i < K_DIM) ? g_py[r * 512 + i] : 0.0f;
        } else if (tid < 96) {
            int n = tid - 32;
            int j = j0 + n;
            pbx[n] = (j < K_DIM) ? g_px[r * 512 + j] : 0.0f;
            pby[n] = (j < K_DIM) ? g_py[r * 512 + j] : 0.0f;
        }

        // load mappings
        int anode = tid >> 2;            // 0..31
        int akg   = (tid & 3) * 8;       // 8 consecutive k
        int bnode = tid >> 1;            // 0..63
        int bkg   = (tid & 1) * 16;      // 16 consecutive k
        int gA = i0 + anode;
        int gB = j0 + bnode;
        const float* baseA = (gA < K_DIM) ? &g_xhat[(r * K_DIM + gA) * B_DIM] : 0;
        const float* baseB = (gB < K_DIM) ? &g_xhat[(r * K_DIM + gB) * B_DIM] : 0;

        float acc[4][4];
        #pragma unroll
        for (int uu = 0; uu < 4; uu++)
            #pragma unroll
            for (int vv = 0; vv < 4; vv++) acc[uu][vv] = 0.0f;

        for (int chunk = 0; chunk < 4; chunk++) {
            int ka = chunk * 32 + akg;
            int kb = chunk * 32 + bkg;
            float4 a0 = make_float4(0.f, 0.f, 0.f, 0.f), a1 = a0;
            float4 b0 = a0, b1 = a0, b2 = a0, b3 = a0;
            if (baseA) { a0 = *(const float4*)(baseA + ka); a1 = *(const float4*)(baseA + ka + 4); }
            if (baseB) {
                b0 = *(const float4*)(baseB + kb);      b1 = *(const float4*)(baseB + kb + 4);
                b2 = *(const float4*)(baseB + kb + 8);  b3 = *(const float4*)(baseB + kb + 12);
            }
            As[akg + 0][anode] = a0.x; As[akg + 1][anode] = a0.y; As[akg + 2][anode] = a0.z; As[akg + 3][anode] = a0.w;
            As[akg + 4][anode] = a1.x; As[akg + 5][anode] = a1.y; As[akg + 6][anode] = a1.z; As[akg + 7][anode] = a1.w;
            Bs[bkg +  0][bnode] = b0.x; Bs[bkg +  1][bnode] = b0.y; Bs[bkg +  2][bnode] = b0.z; Bs[bkg +  3][bnode] = b0.w;
            Bs[bkg +  4][bnode] = b1.x; Bs[bkg +  5][bnode] = b1.y; Bs[bkg +  6][bnode] = b1.z; Bs[bkg +  7][bnode] = b1.w;
            Bs[bkg +  8][bnode] = b2.x; Bs[bkg +  9][bnode] = b2.y; Bs[bkg + 10][bnode] = b2.z; Bs[bkg + 11][bnode] = b2.w;
            Bs[bkg + 12][bnode] = b3.x; Bs[bkg + 13][bnode] = b3.y; Bs[bkg + 14][bnode] = b3.z; Bs[bkg + 15][bnode] = b3.w;
            __syncthreads();

            #pragma unroll 8
            for (int kk = 0; kk < 32; kk++) {
                float4 a4 = *(const float4*)&As[kk][ty * 4];
                float4 b4 = *(const float4*)&Bs[kk][tx * 4];
                float av[4] = {a4.x, a4.y, a4.z, a4.w};
                float bv[4] = {b4.x, b4.y, b4.z, b4.w};
                #pragma unroll
                for (int uu = 0; uu < 4; uu++)
                    #pragma unroll
                    for (int vv = 0; vv < 4; vv++)
                        acc[uu][vv] = fmaf(av[uu], bv[vv], acc[uu][vv]);
            }
            __syncthreads();
        }

        // pair statistics — fp32 per-thread + fp32 warp reduce (fp64 only at block/global combine)
        float sr = 0.0f, sd = 0.0f, srr = 0.0f, sdd = 0.0f, srd = 0.0f;
        #pragma unroll
        for (int uu = 0; uu < 4; uu++) {
            int iloc = ty * 4 + uu;
            int i = i0 + iloc;
            #pragma unroll
            for (int vv = 0; vv < 4; vv++) {
                int jloc = tx * 4 + vv;
                int j = j0 + jloc;
                if (i < K_DIM && j < K_DIM && i > j) {
                    float cr = acc[uu][vv];
                    float dx = pax[iloc] - pbx[jloc];
                    float dy = pay[iloc] - pby[jloc];
                    float ds = 1.0f / (sqrtf(dx * dx + dy * dy) + 1.0f);
                    sr  += cr;
                    sd  += ds;
                    srr = fmaf(cr, cr, srr);
                    sdd = fmaf(ds, ds, sdd);
                    srd = fmaf(cr, ds, srd);
                }
            }
        }
        #pragma unroll
        for (int o = 16; o > 0; o >>= 1) {
            sr  += __shfl_down_sync(0xFFFFFFFFu, sr,  o);
            sd  += __shfl_down_sync(0xFFFFFFFFu, sd,  o);
            srr += __shfl_down_sync(0xFFFFFFFFu, srr, o);
            sdd += __shfl_down_sync(0xFFFFFFFFu, sdd, o);
            srd += __shfl_down_sync(0xFFFFFFFFu, srd, o);
        }
        if (lane == 0) {
            redbuf[wid][0] = sr;  redbuf[wid][1] = sd;  redbuf[wid][2] = srr;
            redbuf[wid][3] = sdd; redbuf[wid][4] = srd;
        }
        __syncthreads();
        if (tid < 5) {
            double a5 = (double)redbuf[0][tid] + (double)redbuf[1][tid]
                      + (double)redbuf[2][tid] + (double)redbuf[3][tid];
            atomicAdd(&g_sums[r][tid], a5);
        }
        __syncthreads();
    }

    // ---------- phase 3: last block finalizes ----------
    __syncthreads();
    if (tid == 0) {
        __threadfence();
        unsigned old = atomicAdd(&g_fin, 1u);
        sLast = (old == (unsigned)GRID - 1u) ? 1 : 0;
    }
    __syncthreads();
    if (sLast && tid == 0) {
        g_bar  = 0u;                      // reset for next replay (all blocks done)
        g_fin  = 0u;
        g_next = 0u;
        __threadfence();
        double acc = 0.0;
        for (int i = 0; i < NRUNS; i++) {
            volatile double* ps = &g_sums[i][0];
            double sr = ps[0], sd = ps[1], srr = ps[2], sdd = ps[3], srd = ps[4];
            double P = NPAIRS;
            double ca  = srr - sr * sr / P;
            double cb  = sdd - sd * sd / P;
            double cab = srd - sr * sd / P;
            acc += (1.0 - cab / sqrt(ca * cb)) * 0.5;
        }
        out[0] = (float)(acc / (double)NRUNS);
    }
}

// ---------------- launch ----------------
extern "C" void kernel_launch(void* const* d_in, const int* in_sizes, int n_in,
                              void* d_out, int out_size) {
    const float* feat  = (const float*)d_in[0];   // [128, 100000]
    const float* pos   = (const float*)d_in[1];   // [100000, 2]
    const int*   neigh = (const int*)  d_in[2];   // [100, 500]
    float* out = (float*)d_out;

    k_all<<<GRID, TPB>>>(feat, pos, neigh, out);
}